// round 12
// baseline (speedup 1.0000x reference)
#include <cuda_runtime.h>
#include <cuda_bf16.h>
#include <cstdint>

#define TPB 256
#define NPS 10
#define O_W1UH 0
#define O_W1UL 32768
#define O_W2H  65536
#define O_W2L  98304
#define O_X    131072
#define O_W1XL 163840
#define O_SCRA 196608
#define O_SCRB 213504
#define O_B1   230400
#define SMEM_TOTAL 231424

__device__ __forceinline__ uint32_t s2u(const void* p){
  uint32_t a; asm("{ .reg .u64 t; cvta.to.shared.u64 t,%1; cvt.u32.u64 %0,t; }":"=r"(a):"l"(p)); return a;
}
__device__ __forceinline__ uint32_t pk2(float lo, float hi){
  uint32_t r; asm("cvt.rn.bf16x2.f32 %0,%1,%2;":"=r"(r):"f"(hi),"f"(lo)); return r;
}
__device__ __forceinline__ void pkhl(float a, float b, uint32_t& h, uint32_t& l){
  h = pk2(a, b);
  float ah = __uint_as_float(h << 16), bh = __uint_as_float(h & 0xffff0000u);
  l = pk2(a - ah, b - bh);
}
__device__ __forceinline__ void pack8(const float* s, uint32_t* h, uint32_t* l){
  pkhl(s[0],s[1],h[0],l[0]); pkhl(s[2],s[3],h[1],l[1]);
  pkhl(s[4],s[5],h[2],l[2]); pkhl(s[6],s[7],h[3],l[3]);
}
__device__ __forceinline__ int swo(int r, int cb){ return r*128 + (cb ^ ((r&7)<<4)); }

// non-volatile: register-only op, deps carried by constraints -> ptxas may schedule
#define MMA(d,a,b0,b1) asm( \
  "mma.sync.aligned.m16n8k16.row.col.f32.bf16.bf16.f32 {%0,%1,%2,%3},{%4,%5,%6,%7},{%8,%9},{%0,%1,%2,%3};" \
  :"+f"((d)[0]),"+f"((d)[1]),"+f"((d)[2]),"+f"((d)[3]) \
  :"r"((a)[0]),"r"((a)[1]),"r"((a)[2]),"r"((a)[3]),"r"(b0),"r"(b1))
#define LDSM(r0,r1,r2,r3,ad) asm volatile( \
  "ldmatrix.sync.aligned.m8n8.x4.shared.b16 {%0,%1,%2,%3},[%4];" \
  :"=r"(r0),"=r"(r1),"=r"(r2),"=r"(r3):"r"(ad))
#define LDSMT(r0,r1,r2,r3,ad) asm volatile( \
  "ldmatrix.sync.aligned.m8n8.x4.trans.shared.b16 {%0,%1,%2,%3},[%4];" \
  :"=r"(r0),"=r"(r1),"=r"(r2),"=r"(r3):"r"(ad))

// p[m, wg-half 128h] = A(src[64] fp32) @ W2^T ; pack A per k-chunk, tp-inner for ILP
#define PGEMM_F(SRC) do { \
  _Pragma("unroll") for (int i_=0;i_<64;i_++) p[i_]=0.f; \
  _Pragma("unroll") for (int j_=0;j_<4;j_++){ \
    uint32_t aH4[4],aL4[4]; pack8((SRC)+8*j_,aH4,aL4); \
    _Pragma("unroll") for (int tp_=0;tp_<8;tp_++){ int hb_=wg*128+16*tp_; \
      uint32_t b0,b1r,b2,b3,c0,c1,c2,c3; \
      LDSM(b0,b1r,b2,b3, smb+O_W2H+swo(hb_+prow,32*j_+pcol)); \
      LDSM(c0,c1,c2,c3, smb+O_W2L+swo(hb_+prow,32*j_+pcol)); \
      MMA(p+8*tp_,aH4,b0,b1r); MMA(p+8*tp_+4,aH4,b2,b3); \
      MMA(p+8*tp_,aL4,b0,b1r); MMA(p+8*tp_+4,aL4,b2,b3); \
      MMA(p+8*tp_,aH4,c0,c1);  MMA(p+8*tp_+4,aH4,c2,c3); \
  } } } while(0)

// one k-chunk of the d=64 GEMM (trans B), np-inner, alternating accumulators
#define WCHUNK(BH,BL,J2,YH,YL) do { int kb_=wg*128+16*(J2); \
  _Pragma("unroll") for (int np_=0;np_<4;np_++){ \
    uint32_t b0,b1r,b2,b3,c0,c1,c2,c3; \
    LDSMT(b0,b1r,b2,b3, smb+(BH)+swo(kb_+trow,32*np_+tcol)); \
    LDSMT(c0,c1,c2,c3, smb+(BL)+swo(kb_+trow,32*np_+tcol)); \
    MMA(w+8*np_,YH,b0,b1r); MMA(w+8*np_+4,YH,b2,b3); \
    MMA(w+8*np_,YL,b0,b1r); MMA(w+8*np_+4,YL,b2,b3); \
    MMA(w+8*np_,YH,c0,c1);  MMA(w+8*np_+4,YH,c2,c3); \
  } } while(0)

#define SCR_ST(SB) do { _Pragma("unroll") for (int nt=0;nt<8;nt++){ int col=8*nt+2*tig; \
  *(float2*)((SB)+rl*66+col)     = make_float2(w[4*nt],  w[4*nt+1]); \
  *(float2*)((SB)+(rl+8)*66+col) = make_float2(w[4*nt+2],w[4*nt+3]); } } while(0)
#define SCR_ADD(SB) do { _Pragma("unroll") for (int nt=0;nt<8;nt++){ int col=8*nt+2*tig; \
  float2 pa=*(const float2*)((SB)+rl*66+col), pb=*(const float2*)((SB)+(rl+8)*66+col); \
  w[4*nt]+=pa.x; w[4*nt+1]+=pa.y; w[4*nt+2]+=pb.x; w[4*nt+3]+=pb.y; } } while(0)

__global__ __launch_bounds__(TPB, 1)
void irb(const float* __restrict__ gx,  const float* __restrict__ gu,
         const float* __restrict__ glp, const float* __restrict__ gve,
         const float* __restrict__ gW1x,const float* __restrict__ gW1u,
         const float* __restrict__ gb1, const float* __restrict__ gW2,
         const float* __restrict__ gb2, float* __restrict__ out, int B)
{
  extern __shared__ char sm[];
  const uint32_t smb = s2u(sm);
  const int tid = threadIdx.x, lane = tid & 31, warp = tid >> 5;
  const int wg = warp >> 2, wr = warp & 3, g = lane >> 2, tig = lane & 3;
  const int rl = wr*16 + g;
  const int growl = blockIdx.x*64 + rl;
  float* scrA = (float*)(sm + O_SCRA);
  float* scrB = (float*)(sm + O_SCRB);
  float* myscr = wg ? scrB : scrA;
  float* otscr = wg ? scrA : scrB;
  float* sB1 = (float*)(sm + O_B1);
  float* sS  = (float*)(sm + O_X) + warp*2048 + lane;   // value i at sS[i*32]

  // weights -> smem bf16 hi/lo, [h][d] 128B rows, XOR swizzle
  __nv_bfloat16* s16 = (__nv_bfloat16*)sm;
  for (int i = tid; i < 256*64; i += TPB) {          // W2 [H][D]
    int h = i >> 6, d = i & 63, o = swo(h, 2*d) >> 1;
    float v = gW2[i];
    __nv_bfloat16 bh = __float2bfloat16_rn(v);
    s16[(O_W2H>>1)+o] = bh;
    s16[(O_W2L>>1)+o] = __float2bfloat16_rn(v - __bfloat162float(bh));
  }
  for (int i = tid; i < 64*256; i += TPB) {          // W1u, W1x [D][H] -> [h][d]
    int d = i >> 8, h = i & 255, o = swo(h, 2*d) >> 1;
    float v = gW1u[i];
    __nv_bfloat16 bh = __float2bfloat16_rn(v);
    s16[(O_W1UH>>1)+o] = bh;
    s16[(O_W1UL>>1)+o] = __float2bfloat16_rn(v - __bfloat162float(bh));
    float w_ = gW1x[i];
    __nv_bfloat16 wh = __float2bfloat16_rn(w_);
    s16[(O_X>>1)+o] = wh;
    s16[(O_W1XL>>1)+o] = __float2bfloat16_rn(w_ - __bfloat162float(wh));
  }
  for (int i = tid; i < 256; i += TPB) sB1[i] = gb1[i];
  {
    const float4* xs = (const float4*)(gx + (size_t)blockIdx.x*64*64);
    float4* xo = (float4*)(out + (size_t)blockIdx.x*64*64);
    for (int i = tid; i < 64*16; i += TPB) xo[i] = xs[i];
  }

  // ve in C-fragment layout
  float vC[32];
  {
    const float* v0 = gve + (size_t)growl*64;
    #pragma unroll
    for (int nt = 0; nt < 8; nt++) {
      float2 a = *(const float2*)(v0 + 8*nt + 2*tig);
      float2 b = *(const float2*)(v0 + 512 + 8*nt + 2*tig);
      vC[4*nt] = a.x; vC[4*nt+1] = a.y; vC[4*nt+2] = b.x; vC[4*nt+3] = b.y;
    }
  }
  // xu A-fragments hi/lo, k = [x | u]
  uint32_t xh[32], xl[32];
  #pragma unroll
  for (int j = 0; j < 8; j++) {
    const float* src = (j < 4 ? gx : gu) + (size_t)growl*64 + 16*(j & 3);
    float2 v0 = *(const float2*)(src + 2*tig);
    float2 v1 = *(const float2*)(src + 512 + 2*tig);
    float2 v2 = *(const float2*)(src + 8 + 2*tig);
    float2 v3 = *(const float2*)(src + 512 + 8 + 2*tig);
    pkhl(v0.x,v0.y, xh[4*j],  xl[4*j]);   pkhl(v1.x,v1.y, xh[4*j+1],xl[4*j+1]);
    pkhl(v2.x,v2.y, xh[4*j+2],xl[4*j+2]); pkhl(v3.x,v3.y, xh[4*j+3],xl[4*j+3]);
  }
  __syncthreads();

  const int prow = (lane&7) + ((lane>>4)&1)*8, pcol = ((lane>>3)&1)*16;
  const int trow = (lane&7) + ((lane>>3)&1)*8, tcol = ((lane>>4)&1)*16;

  // z-GEMM into p[]
  float p[64];
  #pragma unroll
  for (int i = 0; i < 64; i++) p[i] = 0.f;
  #pragma unroll
  for (int j = 0; j < 8; j++) {
    uint32_t bh_ = smb + (j < 4 ? O_X    : O_W1UH);
    uint32_t bl_ = smb + (j < 4 ? O_W1XL : O_W1UL);
    int jb = 32*(j & 3);
    #pragma unroll
    for (int tp = 0; tp < 8; tp++) {
      int hb = wg*128 + 16*tp;
      uint32_t b0,b1r,b2,b3,c0,c1,c2,c3;
      LDSM(b0,b1r,b2,b3, bh_ + swo(hb+prow, jb+pcol));
      LDSM(c0,c1,c2,c3, bl_ + swo(hb+prow, jb+pcol));
      MMA(p+8*tp,  xh+4*j,b0,b1r); MMA(p+8*tp+4,xh+4*j,b2,b3);
      MMA(p+8*tp,  xl+4*j,b0,b1r); MMA(p+8*tp+4,xl+4*j,b2,b3);
      MMA(p+8*tp,  xh+4*j,c0,c1);  MMA(p+8*tp+4,xh+4*j,c2,c3);
    }
  }
  __syncthreads();   // z done; W1x region becomes s slab

  // activation: s -> slab (interleaved, conflict-free), ha -> p[]
  #pragma unroll
  for (int nt = 0; nt < 16; nt++) {
    int col = wg*128 + 8*nt + 2*tig;
    float2 bv = *(const float2*)(sB1 + col);
    #pragma unroll
    for (int e = 0; e < 4; e++) {
      float zz = p[4*nt+e] + ((e & 1) ? bv.y : bv.x);
      float ex = __expf(zz);
      sS[(4*nt+e)*32] = zz > 0.f ? 1.f : ex;
      p[4*nt+e] = zz > 0.f ? zz : ex - 1.f;
    }
  }

  // g-GEMM (A = ha in p[]), split-K over h-halves
  float w[32];
  #pragma unroll
  for (int i = 0; i < 32; i++) w[i] = 0.f;
  #pragma unroll
  for (int j2 = 0; j2 < 8; j2++) {
    uint32_t yh4[4], yl4[4];
    pack8(p + 8*j2, yh4, yl4);
    WCHUNK(O_W2H, O_W2L, j2, yh4, yl4);
  }
  SCR_ST(myscr);
  __syncthreads();
  if (wg == 0) {      // v = u + g + b2
    SCR_ADD(otscr);
    const float* u0 = gu + (size_t)growl*64;
    float* vo = out + (size_t)B*64 + (size_t)growl*64;
    #pragma unroll
    for (int nt = 0; nt < 8; nt++) {
      int col = 8*nt + 2*tig;
      float2 ua = *(const float2*)(u0 + col);
      float2 ub = *(const float2*)(u0 + 512 + col);
      float2 bb = *(const float2*)(gb2 + col);
      *(float2*)(vo + col)       = make_float2(ua.x + w[4*nt]   + bb.x, ua.y + w[4*nt+1] + bb.y);
      *(float2*)(vo + 512 + col) = make_float2(ub.x + w[4*nt+2] + bb.x, ub.y + w[4*nt+3] + bb.y);
    }
  }
  __syncthreads();

  // p1 = ve @ W2^T
  PGEMM_F(vC);

  // power series; each wg accumulates the dot of ITS partial w (linearity)
  float lgdl = 0.f, lgdh = 0.f;
  #pragma unroll 1
  for (int k = 1; k <= NPS; k++) {
    #pragma unroll
    for (int i = 0; i < 32; i++) w[i] = 0.f;
    #pragma unroll
    for (int j2 = 0; j2 < 8; j2++) {
      float y8[8];
      #pragma unroll
      for (int e = 0; e < 8; e++) y8[e] = p[8*j2+e] * sS[(8*j2+e)*32];
      uint32_t yh4[4], yl4[4];
      pack8(y8, yh4, yl4);
      WCHUNK(O_W1UH, O_W1UL, j2, yh4, yl4);
    }
    float dl = 0.f, dh = 0.f;
    #pragma unroll
    for (int nt = 0; nt < 8; nt++) {
      dl = fmaf(w[4*nt],   vC[4*nt],   fmaf(w[4*nt+1], vC[4*nt+1], dl));
      dh = fmaf(w[4*nt+2], vC[4*nt+2], fmaf(w[4*nt+3], vC[4*nt+3], dh));
    }
    float ck = ((k & 1) ? 1.f : -1.f) / (float)k;
    lgdl = fmaf(ck, dl, lgdl); lgdh = fmaf(ck, dh, lgdh);
    if (k < NPS) {
      SCR_ST(myscr);
      __syncthreads();
      SCR_ADD(otscr);         // both wgs now hold full w
      __syncthreads();        // all reads done before next iter's writes
      PGEMM_F(w);
    }
  }

  // reduce over tig lanes, then merge the two wgs' logdet partials
  lgdl += __shfl_xor_sync(0xffffffffu, lgdl, 1); lgdl += __shfl_xor_sync(0xffffffffu, lgdl, 2);
  lgdh += __shfl_xor_sync(0xffffffffu, lgdh, 1); lgdh += __shfl_xor_sync(0xffffffffu, lgdh, 2);
  __syncthreads();
  if (wg == 1 && tig == 0) { scrA[rl] = lgdl; scrA[rl+8] = lgdh; }
  __syncthreads();
  if (wg == 0 && tig == 0) {
    out[(size_t)2*B*64 + growl]     = glp[growl]     - (lgdl + scrA[rl]);
    out[(size_t)2*B*64 + growl + 8] = glp[growl + 8] - (lgdh + scrA[rl+8]);
  }
}

extern "C" void kernel_launch(void* const* d_in, const int* in_sizes, int n_in,
                              void* d_out, int out_size)
{
  const float* gx   = (const float*)d_in[0];
  const float* gu   = (const float*)d_in[1];
  const float* glp  = (const float*)d_in[2];
  const float* gve  = (const float*)d_in[3];
  const float* gW1x = (const float*)d_in[4];
  const float* gW1u = (const float*)d_in[5];
  const float* gb1  = (const float*)d_in[6];
  const float* gW2  = (const float*)d_in[7];
  const float* gb2  = (const float*)d_in[8];
  float* out = (float*)d_out;

  int B = in_sizes[0] / 64;          // 131072
  int grid = B / 64;                 // 2048

  cudaFuncSetAttribute(irb, cudaFuncAttributeMaxDynamicSharedMemorySize, SMEM_TOTAL);
  irb<<<grid, TPB, SMEM_TOTAL>>>(gx, gu, glp, gve, gW1x, gW1u, gb1, gW2, gb2, out, B);
}

// round 13
// speedup vs baseline: 1.4820x; 1.4820x over previous
#include <cuda_runtime.h>
#include <cuda_bf16.h>
#include <cstdint>

#define TPB 256
#define NPS 10
#define O_W1UH 0
#define O_W1UL 32768
#define O_W2H  65536
#define O_W2L  98304
#define O_X    131072
#define O_W1XL 163840
#define O_SCR  198656
#define O_B1   215552
#define SMEM_TOTAL 216576

__device__ __forceinline__ uint32_t s2u(const void* p){
  uint32_t a; asm("{ .reg .u64 t; cvta.to.shared.u64 t,%1; cvt.u32.u64 %0,t; }":"=r"(a):"l"(p)); return a;
}
__device__ __forceinline__ uint32_t pk2(float lo, float hi){
  uint32_t r; asm("cvt.rn.bf16x2.f32 %0,%1,%2;":"=r"(r):"f"(hi),"f"(lo)); return r;
}
__device__ __forceinline__ void pkhl(float a, float b, uint32_t& h, uint32_t& l){
  h = pk2(a, b);
  float ah = __uint_as_float(h << 16), bh = __uint_as_float(h & 0xffff0000u);
  l = pk2(a - ah, b - bh);
}
__device__ __forceinline__ int swo(int r, int cb){ return r*128 + (cb ^ ((r&7)<<4)); }

#define MMA(d,a,b0,b1) asm volatile( \
  "mma.sync.aligned.m16n8k16.row.col.f32.bf16.bf16.f32 {%0,%1,%2,%3},{%4,%5,%6,%7},{%8,%9},{%0,%1,%2,%3};" \
  :"+f"((d)[0]),"+f"((d)[1]),"+f"((d)[2]),"+f"((d)[3]) \
  :"r"((a)[0]),"r"((a)[1]),"r"((a)[2]),"r"((a)[3]),"r"(b0),"r"(b1))
#define LDSM(r0,r1,r2,r3,ad) asm volatile( \
  "ldmatrix.sync.aligned.m8n8.x4.shared.b16 {%0,%1,%2,%3},[%4];" \
  :"=r"(r0),"=r"(r1),"=r"(r2),"=r"(r3):"r"(ad))
#define LDSMT(r0,r1,r2,r3,ad) asm volatile( \
  "ldmatrix.sync.aligned.m8n8.x4.trans.shared.b16 {%0,%1,%2,%3},[%4];" \
  :"=r"(r0),"=r"(r1),"=r"(r2),"=r"(r3):"r"(ad))

// one j-chunk (k=16) against TWO adjacent 16-h tiles: 4 accumulators, RAW dist 4
#define ZPAIR(BH,BL,JB,AH4,AL4,TPH) do { int hb_=wg*128+32*(TPH); \
  uint32_t b0,b1r,b2,b3,c0,c1,c2,c3,d0,d1,d2,d3,e0,e1,e2,e3; \
  LDSM(b0,b1r,b2,b3, (BH)+swo(hb_+prow,(JB)+pcol)); \
  LDSM(c0,c1,c2,c3, (BL)+swo(hb_+prow,(JB)+pcol)); \
  LDSM(d0,d1,d2,d3, (BH)+swo(hb_+16+prow,(JB)+pcol)); \
  LDSM(e0,e1,e2,e3, (BL)+swo(hb_+16+prow,(JB)+pcol)); \
  float *q0=p+16*(TPH), *q1=q0+4, *q2=q0+8, *q3=q0+12; \
  MMA(q0,AH4,b0,b1r); MMA(q1,AH4,b2,b3); MMA(q2,AH4,d0,d1); MMA(q3,AH4,d2,d3); \
  MMA(q0,AL4,b0,b1r); MMA(q1,AL4,b2,b3); MMA(q2,AL4,d0,d1); MMA(q3,AL4,d2,d3); \
  MMA(q0,AH4,c0,c1);  MMA(q1,AH4,c2,c3); MMA(q2,AH4,e0,e1); MMA(q3,AH4,e2,e3); \
} while(0)

// p[m, wg-half 128h] = A(aH/aL, k=64) @ W2^T
#define PGEMM() do { \
  _Pragma("unroll") for (int i_=0;i_<64;i_++) p[i_]=0.f; \
  _Pragma("unroll") for (int j_=0;j_<4;j_++){ \
    _Pragma("unroll") for (int th_=0;th_<4;th_++) \
      ZPAIR(smb+O_W2H, smb+O_W2L, 32*j_, aH+4*j_, aL+4*j_, th_); \
  } } while(0)

// one k-chunk (16 h) of the d=64 GEMM (trans B): 4 accumulators, RAW dist 4
#define WCHUNK(BH,BL,J2,YH,YL) do { int kb_=wg*128+16*(J2); \
  _Pragma("unroll") for (int nh_=0;nh_<2;nh_++){ \
    uint32_t b0,b1r,b2,b3,c0,c1,c2,c3,d0,d1,d2,d3,e0,e1,e2,e3; \
    LDSMT(b0,b1r,b2,b3, smb+(BH)+swo(kb_+trow,64*nh_+tcol)); \
    LDSMT(c0,c1,c2,c3, smb+(BL)+swo(kb_+trow,64*nh_+tcol)); \
    LDSMT(d0,d1,d2,d3, smb+(BH)+swo(kb_+trow,64*nh_+32+tcol)); \
    LDSMT(e0,e1,e2,e3, smb+(BL)+swo(kb_+trow,64*nh_+32+tcol)); \
    float *q0=w+16*nh_, *q1=q0+4, *q2=q0+8, *q3=q0+12; \
    MMA(q0,YH,b0,b1r); MMA(q1,YH,b2,b3); MMA(q2,YH,d0,d1); MMA(q3,YH,d2,d3); \
    MMA(q0,YL,b0,b1r); MMA(q1,YL,b2,b3); MMA(q2,YL,d0,d1); MMA(q3,YL,d2,d3); \
    MMA(q0,YH,c0,c1);  MMA(q1,YH,c2,c3); MMA(q2,YH,e0,e1); MMA(q3,YH,e2,e3); \
  } } while(0)

#define SCR_ST() do { _Pragma("unroll") for (int nt=0;nt<8;nt++){ int col=8*nt+2*tig; \
  *(float2*)(scr+rl*66+col)     = make_float2(w[4*nt],  w[4*nt+1]); \
  *(float2*)(scr+(rl+8)*66+col) = make_float2(w[4*nt+2],w[4*nt+3]); } } while(0)
#define SCR_ADD() do { _Pragma("unroll") for (int nt=0;nt<8;nt++){ int col=8*nt+2*tig; \
  float2 pa=*(const float2*)(scr+rl*66+col), pb=*(const float2*)(scr+(rl+8)*66+col); \
  w[4*nt]+=pa.x; w[4*nt+1]+=pa.y; w[4*nt+2]+=pb.x; w[4*nt+3]+=pb.y; } } while(0)
#define SCR_LD() do { _Pragma("unroll") for (int nt=0;nt<8;nt++){ int col=8*nt+2*tig; \
  float2 pa=*(const float2*)(scr+rl*66+col), pb=*(const float2*)(scr+(rl+8)*66+col); \
  w[4*nt]=pa.x; w[4*nt+1]=pa.y; w[4*nt+2]=pb.x; w[4*nt+3]=pb.y; } } while(0)
#define PACK_A(src) do { _Pragma("unroll") for (int j=0;j<4;j++){ \
  pkhl((src)[8*j],  (src)[8*j+1], aH[4*j],  aL[4*j]); \
  pkhl((src)[8*j+2],(src)[8*j+3], aH[4*j+1],aL[4*j+1]); \
  pkhl((src)[8*j+4],(src)[8*j+5], aH[4*j+2],aL[4*j+2]); \
  pkhl((src)[8*j+6],(src)[8*j+7], aH[4*j+3],aL[4*j+3]); } } while(0)

__global__ __launch_bounds__(TPB, 1)
void irb(const float* __restrict__ gx,  const float* __restrict__ gu,
         const float* __restrict__ glp, const float* __restrict__ gve,
         const float* __restrict__ gW1x,const float* __restrict__ gW1u,
         const float* __restrict__ gb1, const float* __restrict__ gW2,
         const float* __restrict__ gb2, float* __restrict__ out, int B)
{
  extern __shared__ char sm[];
  const uint32_t smb = s2u(sm);
  const int tid = threadIdx.x, lane = tid & 31, warp = tid >> 5;
  const int wg = warp >> 2, wr = warp & 3, g = lane >> 2, tig = lane & 3;
  const int rl = wr*16 + g;
  const int growl = blockIdx.x*64 + rl;
  float* scr = (float*)(sm + O_SCR);
  float* sB1 = (float*)(sm + O_B1);

  __nv_bfloat16* s16 = (__nv_bfloat16*)sm;
  for (int i = tid; i < 256*64; i += TPB) {          // W2 [H][D]
    int h = i >> 6, d = i & 63, o = swo(h, 2*d) >> 1;
    float v = gW2[i];
    __nv_bfloat16 bh = __float2bfloat16_rn(v);
    s16[(O_W2H>>1)+o] = bh;
    s16[(O_W2L>>1)+o] = __float2bfloat16_rn(v - __bfloat162float(bh));
  }
  for (int i = tid; i < 64*256; i += TPB) {          // W1u, W1x [D][H] -> [h][d]
    int d = i >> 8, h = i & 255, o = swo(h, 2*d) >> 1;
    float v = gW1u[i];
    __nv_bfloat16 bh = __float2bfloat16_rn(v);
    s16[(O_W1UH>>1)+o] = bh;
    s16[(O_W1UL>>1)+o] = __float2bfloat16_rn(v - __bfloat162float(bh));
    float w_ = gW1x[i];
    __nv_bfloat16 wh = __float2bfloat16_rn(w_);
    s16[(O_X>>1)+o] = wh;
    s16[(O_W1XL>>1)+o] = __float2bfloat16_rn(w_ - __bfloat162float(wh));
  }
  for (int i = tid; i < 256; i += TPB) sB1[i] = gb1[i];
  {
    const float4* xs = (const float4*)(gx + (size_t)blockIdx.x*64*64);
    float4* xo = (float4*)(out + (size_t)blockIdx.x*64*64);
    for (int i = tid; i < 64*16; i += TPB) xo[i] = xs[i];
  }

  float vC[32];
  {
    const float* v0 = gve + (size_t)growl*64;
    #pragma unroll
    for (int nt = 0; nt < 8; nt++) {
      float2 a = *(const float2*)(v0 + 8*nt + 2*tig);
      float2 b = *(const float2*)(v0 + 512 + 8*nt + 2*tig);
      vC[4*nt] = a.x; vC[4*nt+1] = a.y; vC[4*nt+2] = b.x; vC[4*nt+3] = b.y;
    }
  }
  uint32_t xh[32], xl[32];
  #pragma unroll
  for (int j = 0; j < 8; j++) {
    const float* src = (j < 4 ? gx : gu) + (size_t)growl*64 + 16*(j & 3);
    float2 v0 = *(const float2*)(src + 2*tig);
    float2 v1 = *(const float2*)(src + 512 + 2*tig);
    float2 v2 = *(const float2*)(src + 8 + 2*tig);
    float2 v3 = *(const float2*)(src + 512 + 8 + 2*tig);
    pkhl(v0.x,v0.y, xh[4*j],  xl[4*j]);   pkhl(v1.x,v1.y, xh[4*j+1],xl[4*j+1]);
    pkhl(v2.x,v2.y, xh[4*j+2],xl[4*j+2]); pkhl(v3.x,v3.y, xh[4*j+3],xl[4*j+3]);
  }
  __syncthreads();

  const int prow = (lane&7) + ((lane>>4)&1)*8, pcol = ((lane>>3)&1)*16;
  const int trow = (lane&7) + ((lane>>3)&1)*8, tcol = ((lane>>4)&1)*16;

  // z-GEMM into p[]
  float p[64];
  #pragma unroll
  for (int i = 0; i < 64; i++) p[i] = 0.f;
  #pragma unroll
  for (int j = 0; j < 8; j++) {
    uint32_t bh_ = smb + (j < 4 ? O_X    : O_W1UH);
    uint32_t bl_ = smb + (j < 4 ? O_W1XL : O_W1UL);
    int jb = 32*(j & 3);
    #pragma unroll
    for (int th = 0; th < 4; th++)
      ZPAIR(bh_, bl_, jb, xh+4*j, xl+4*j, th);
  }
  __syncthreads();   // z done; W1x region becomes s slab

  // activation: s -> per-thread slab, ha -> p[]
  float* sS = (float*)(sm + O_X) + tid*66;
  #pragma unroll
  for (int nt = 0; nt < 16; nt++) {
    int col = wg*128 + 8*nt + 2*tig;
    float2 bv = *(const float2*)(sB1 + col);
    float s4[4];
    #pragma unroll
    for (int e = 0; e < 4; e++) {
      float zz = p[4*nt+e] + ((e & 1) ? bv.y : bv.x);
      float ex = __expf(zz);
      s4[e] = zz > 0.f ? 1.f : ex;
      p[4*nt+e] = zz > 0.f ? zz : ex - 1.f;
    }
    *(float2*)(sS + 4*nt)     = make_float2(s4[0], s4[1]);
    *(float2*)(sS + 4*nt + 2) = make_float2(s4[2], s4[3]);
  }

  // g-GEMM (A = ha in p[]), split-K over h-halves
  float w[32];
  uint32_t aH[16], aL[16];
  #pragma unroll
  for (int i = 0; i < 32; i++) w[i] = 0.f;
  #pragma unroll
  for (int j2 = 0; j2 < 8; j2++) {
    uint32_t yh4[4], yl4[4];
    pkhl(p[8*j2],  p[8*j2+1], yh4[0], yl4[0]); pkhl(p[8*j2+2],p[8*j2+3], yh4[1], yl4[1]);
    pkhl(p[8*j2+4],p[8*j2+5], yh4[2], yl4[2]); pkhl(p[8*j2+6],p[8*j2+7], yh4[3], yl4[3]);
    WCHUNK(O_W2H, O_W2L, j2, yh4, yl4);
  }
  if (wg == 1) SCR_ST();
  __syncthreads();
  if (wg == 0) {      // v = u + g + b2
    SCR_ADD();
    const float* u0 = gu + (size_t)growl*64;
    float* vo = out + (size_t)B*64 + (size_t)growl*64;
    #pragma unroll
    for (int nt = 0; nt < 8; nt++) {
      int col = 8*nt + 2*tig;
      float2 ua = *(const float2*)(u0 + col);
      float2 ub = *(const float2*)(u0 + 512 + col);
      float2 bb = *(const float2*)(gb2 + col);
      *(float2*)(vo + col)       = make_float2(ua.x + w[4*nt]   + bb.x, ua.y + w[4*nt+1] + bb.y);
      *(float2*)(vo + 512 + col) = make_float2(ub.x + w[4*nt+2] + bb.x, ub.y + w[4*nt+3] + bb.y);
    }
  }
  __syncthreads();

  // p1 = ve @ W2^T
  PACK_A(vC);
  PGEMM();

  // power series
  float lgdl = 0.f, lgdh = 0.f;
  #pragma unroll 1
  for (int k = 1; k <= NPS; k++) {
    #pragma unroll
    for (int i = 0; i < 32; i++) w[i] = 0.f;
    #pragma unroll
    for (int j2 = 0; j2 < 8; j2++) {
      float2 sa = *(const float2*)(sS + 8*j2);
      float2 sb = *(const float2*)(sS + 8*j2 + 2);
      float2 sc = *(const float2*)(sS + 8*j2 + 4);
      float2 sd = *(const float2*)(sS + 8*j2 + 6);
      uint32_t yh4[4], yl4[4];
      pkhl(p[8*j2]*sa.x,  p[8*j2+1]*sa.y, yh4[0], yl4[0]);
      pkhl(p[8*j2+2]*sb.x,p[8*j2+3]*sb.y, yh4[1], yl4[1]);
      pkhl(p[8*j2+4]*sc.x,p[8*j2+5]*sc.y, yh4[2], yl4[2]);
      pkhl(p[8*j2+6]*sd.x,p[8*j2+7]*sd.y, yh4[3], yl4[3]);
      WCHUNK(O_W1UH, O_W1UL, j2, yh4, yl4);
    }
    if (wg == 1) SCR_ST();
    __syncthreads();
    if (wg == 0) {
      SCR_ADD();
      float dl = 0.f, dh = 0.f;
      #pragma unroll
      for (int nt = 0; nt < 8; nt++) {
        dl = fmaf(w[4*nt],   vC[4*nt],   fmaf(w[4*nt+1], vC[4*nt+1], dl));
        dh = fmaf(w[4*nt+2], vC[4*nt+2], fmaf(w[4*nt+3], vC[4*nt+3], dh));
      }
      dl += __shfl_xor_sync(0xffffffffu, dl, 1); dl += __shfl_xor_sync(0xffffffffu, dl, 2);
      dh += __shfl_xor_sync(0xffffffffu, dh, 1); dh += __shfl_xor_sync(0xffffffffu, dh, 2);
      float ck = ((k & 1) ? 1.f : -1.f) / (float)k;
      lgdl = fmaf(ck, dl, lgdl); lgdh = fmaf(ck, dh, lgdh);
    }
    if (k < NPS) {
      if (wg == 0) SCR_ST();
      __syncthreads();
      if (wg == 1) SCR_LD();
      PACK_A(w);
      PGEMM();
    }
  }

  if (wg == 0 && tig == 0) {
    out[(size_t)2*B*64 + growl]     = glp[growl]     - lgdl;
    out[(size_t)2*B*64 + growl + 8] = glp[growl + 8] - lgdh;
  }
}

extern "C" void kernel_launch(void* const* d_in, const int* in_sizes, int n_in,
                              void* d_out, int out_size)
{
  const float* gx   = (const float*)d_in[0];
  const float* gu   = (const float*)d_in[1];
  const float* glp  = (const float*)d_in[2];
  const float* gve  = (const float*)d_in[3];
  const float* gW1x = (const float*)d_in[4];
  const float* gW1u = (const float*)d_in[5];
  const float* gb1  = (const float*)d_in[6];
  const float* gW2  = (const float*)d_in[7];
  const float* gb2  = (const float*)d_in[8];
  float* out = (float*)d_out;

  int B = in_sizes[0] / 64;          // 131072
  int grid = B / 64;                 // 2048

  cudaFuncSetAttribute(irb, cudaFuncAttributeMaxDynamicSharedMemorySize, SMEM_TOTAL);
  irb<<<grid, TPB, SMEM_TOTAL>>>(gx, gu, glp, gve, gW1x, gW1u, gb1, gW2, gb2, out, B);
}